// round 16
// baseline (speedup 1.0000x reference)
#include <cuda_runtime.h>
#include <cuda_bf16.h>
#include <math_constants.h>
#include <cstdint>

#define B_   32
#define N_   1024
#define F_   64
#define K_   16
#define P_   128
#define H_   256
#define NPB  4              // points per block
#define M_   64             // GEMM rows per block
#define THR  256            // 8 warps

typedef unsigned long long ull;

// ---------------------------------------------------------------------------
// device scratch (static — no allocation)
// Fragment tables: 16B per (ks, ntile, lane) = {bhi0, bhi1, blo0, blo1}
// ---------------------------------------------------------------------------
__device__ int g_idx[B_ * N_ * K_];
__device__ __align__(16) uint4 g_w1f[2 * 8 * 16 * 32];   // 64 KB
__device__ __align__(16) uint4 g_w2f[2 * 8 * 16 * 32];   // 64 KB (ks_glob = h*8+ks)

// ---------------------------------------------------------------------------
// SMEM layout (dynamic, bytes)
// A image: 64 rows x 128 cols bf16 (256B/row) hi+lo
// H image: 64 rows x 256 cols bf16 (512B/row) hi+lo  (FULL hidden, both halves)
// ---------------------------------------------------------------------------
#define SM_AHI  0            // 16384
#define SM_ALO  16384        // 16384
#define SM_HHI  32768        // 32768
#define SM_HLO  65536        // 32768
#define SM_MISC 98304
#define SM_NBS  (SM_MISC + 0)        // 64 ints
#define SM_CENS (SM_MISC + 256)      // 256 floats
#define SM_B1S  (SM_MISC + 1280)     // 256 floats
#define SM_B2S  (SM_MISC + 2304)     // 128 floats
#define SMEM_TOTAL (SM_MISC + 2816)

// ---------------------------------------------------------------------------
// image addressing, 128-col (256B/row) and 256-col (512B/row) variants.
// 16B chunks XOR-swizzled by row&7 -> conflict-free ldmatrix.
// ---------------------------------------------------------------------------
__device__ __forceinline__ uint32_t img_off(int r, int c)
{
    return (uint32_t)(r * 256) + (uint32_t)((((c >> 3) ^ (r & 7)) << 4) + (c & 7) * 2);
}
__device__ __forceinline__ uint32_t img_addr(uint32_t base, int row, int chunk)
{
    return base + (uint32_t)(row * 256) + (uint32_t)(((chunk ^ (row & 7)) << 4));
}
__device__ __forceinline__ uint32_t img_off256(int r, int c)
{
    return (uint32_t)(r * 512) + (uint32_t)((((c >> 3) ^ (r & 7)) << 4) + (c & 7) * 2);
}
__device__ __forceinline__ uint32_t img_addr256(uint32_t base, int row, int chunk)
{
    return base + (uint32_t)(row * 512) + (uint32_t)(((chunk ^ (row & 7)) << 4));
}

__device__ __forceinline__ uint32_t smem_to_u32(const void* p)
{
    uint32_t a;
    asm("{ .reg .u64 t; cvta.to.shared.u64 t, %1; cvt.u32.u64 %0, t; }"
        : "=r"(a) : "l"(p));
    return a;
}

// ---------------------------------------------------------------------------
// ldmatrix / mma wrappers (baseline PTX, no sm_103a-gated features)
// ---------------------------------------------------------------------------
__device__ __forceinline__ void ldm_x4(uint32_t* r, uint32_t addr)
{
    asm volatile("ldmatrix.sync.aligned.m8n8.x4.shared.b16 {%0,%1,%2,%3}, [%4];"
                 : "=r"(r[0]), "=r"(r[1]), "=r"(r[2]), "=r"(r[3]) : "r"(addr));
}
__device__ __forceinline__ void mma_bf16(float* d, const uint32_t* a,
                                         uint32_t b0, uint32_t b1)
{
    asm volatile(
        "mma.sync.aligned.m16n8k16.row.col.f32.bf16.bf16.f32 "
        "{%0,%1,%2,%3}, {%4,%5,%6,%7}, {%8,%9}, {%0,%1,%2,%3};"
        : "+f"(d[0]), "+f"(d[1]), "+f"(d[2]), "+f"(d[3])
        : "r"(a[0]), "r"(a[1]), "r"(a[2]), "r"(a[3]), "r"(b0), "r"(b1));
}

__device__ __forceinline__ uint32_t pk2(__nv_bfloat16 a, __nv_bfloat16 b)
{
    uint16_t ua = *(uint16_t*)&a, ub = *(uint16_t*)&b;
    return (uint32_t)ua | ((uint32_t)ub << 16);
}
__device__ __forceinline__ void split4(float v0, float v1, float v2, float v3,
                                       ull& hi, ull& lo)
{
    __nv_bfloat16 h0 = __float2bfloat16(v0), h1 = __float2bfloat16(v1);
    __nv_bfloat16 h2 = __float2bfloat16(v2), h3 = __float2bfloat16(v3);
    __nv_bfloat16 l0 = __float2bfloat16(v0 - __bfloat162float(h0));
    __nv_bfloat16 l1 = __float2bfloat16(v1 - __bfloat162float(h1));
    __nv_bfloat16 l2 = __float2bfloat16(v2 - __bfloat162float(h2));
    __nv_bfloat16 l3 = __float2bfloat16(v3 - __bfloat162float(h3));
    hi = (ull)pk2(h0, h1) | ((ull)pk2(h2, h3) << 32);
    lo = (ull)pk2(l0, l1) | ((ull)pk2(l2, l3) << 32);
}
__device__ __forceinline__ void split2(float v0, float v1, uint32_t& hi, uint32_t& lo)
{
    __nv_bfloat16 h0 = __float2bfloat16(v0), h1 = __float2bfloat16(v1);
    __nv_bfloat16 l0 = __float2bfloat16(v0 - __bfloat162float(h0));
    __nv_bfloat16 l1 = __float2bfloat16(v1 - __bfloat162float(h1));
    hi = pk2(h0, h1); lo = pk2(l0, l1);
}
__device__ __forceinline__ float gelu_exact(float x)
{
    return 0.5f * x * (1.0f + erff(x * 0.70710678118654752440f));
}

// ---------------------------------------------------------------------------
// Kernel 0: weight prep — build B-fragment tables (split bf16 hi/lo).
// Layout identical to R14 (W2: ks_glob = h*8+ks merges the chunk index).
// ---------------------------------------------------------------------------
__global__ __launch_bounds__(256) void prep_kernel(const float* __restrict__ W1,
                                                   const float* __restrict__ W2)
{
    int i = blockIdx.x * 256 + threadIdx.x;      // 0 .. 16383
    int mat  = i >> 13;
    int rem  = i & 8191;
    int h    = rem >> 12;
    int ks   = (rem >> 9) & 7;
    int nt   = (rem >> 5) & 15;
    int lane = rem & 31;

    int np = nt * 8 + (lane >> 2);
    int k0 = ks * 16 + (lane & 3) * 2;

    float v[4];
    if (mat == 0) {
        int n = h * 128 + np;
        v[0] = W1[(k0 + 0) * H_ + n];
        v[1] = W1[(k0 + 1) * H_ + n];
        v[2] = W1[(k0 + 8) * H_ + n];
        v[3] = W1[(k0 + 9) * H_ + n];
    } else {
        int j = h * 128 + k0;
        v[0] = W2[(j + 0) * P_ + np];
        v[1] = W2[(j + 1) * P_ + np];
        v[2] = W2[(j + 8) * P_ + np];
        v[3] = W2[(j + 9) * P_ + np];
    }
    __nv_bfloat16 hi0 = __float2bfloat16(v[0]), hi1 = __float2bfloat16(v[1]);
    __nv_bfloat16 hi2 = __float2bfloat16(v[2]), hi3 = __float2bfloat16(v[3]);
    __nv_bfloat16 lo0 = __float2bfloat16(v[0] - __bfloat162float(hi0));
    __nv_bfloat16 lo1 = __float2bfloat16(v[1] - __bfloat162float(hi1));
    __nv_bfloat16 lo2 = __float2bfloat16(v[2] - __bfloat162float(hi2));
    __nv_bfloat16 lo3 = __float2bfloat16(v[3] - __bfloat162float(hi3));

    uint4 frag;
    frag.x = pk2(hi0, hi1);
    frag.y = pk2(hi2, hi3);
    frag.z = pk2(lo0, lo1);
    frag.w = pk2(lo2, lo3);

    int idx = (((h * 8 + ks) * 16) + nt) * 32 + lane;
    if (mat == 0) g_w1f[idx] = frag;
    else          g_w2f[idx] = frag;
}

// ---------------------------------------------------------------------------
// Kernel 1: KNN (proven correct, unchanged)
// ---------------------------------------------------------------------------
__global__ __launch_bounds__(256) void knn_kernel(const float* __restrict__ points)
{
    __shared__ float4 pts[N_];
    int b = blockIdx.x >> 2;
    int rowbase = (blockIdx.x & 3) << 8;
    const float* P = points + (size_t)b * N_ * 3;
    for (int i = threadIdx.x; i < N_; i += 256) {
        float x = P[i * 3 + 0], y = P[i * 3 + 1], z = P[i * 3 + 2];
        pts[i] = make_float4(x, y, z, x * x + y * y + z * z);
    }
    __syncthreads();

    int n = rowbase + threadIdx.x;
    float4 pn = pts[n];

    float dist[K_ + 1];
    int   nbr[K_ + 1];
#pragma unroll
    for (int j = 0; j <= K_; j++) { dist[j] = CUDART_INF_F; nbr[j] = 0; }
    float worst = CUDART_INF_F;

    for (int m = 0; m < N_; m++) {
        float4 pm = pts[m];
        float dot = pn.x * pm.x + pn.y * pm.y + pn.z * pm.z;
        float d = pn.w - 2.0f * dot + pm.w + 1e-5f;
        if (d < worst) {
            int j = K_;
            for (; j > 0; j--) {
                if (dist[j - 1] > d) { dist[j] = dist[j - 1]; nbr[j] = nbr[j - 1]; }
                else break;
            }
            dist[j] = d; nbr[j] = m;
            worst = dist[K_];
        }
    }

    int* o = g_idx + ((size_t)b * N_ + n) * K_;
#pragma unroll
    for (int k = 0; k < K_; k++) o[k] = nbr[k + 1];
}

// ---------------------------------------------------------------------------
// Kernel 2: fused edge-MLP via split-bf16 mma.sync (3 products, fp32 acc).
// Restructured: phase1 both halves -> full H image -> ONE sync -> phase2 as
// a single 16-ks loop. Fewer barriers; e-accumulators born after d dies.
// MMA inner ordering identical to R14 (proven fastest).
// ---------------------------------------------------------------------------
__global__ __launch_bounds__(THR, 2) void mlp_kernel(
    const float* __restrict__ features,
    const float* __restrict__ b1, const float* __restrict__ b2,
    float* __restrict__ out)
{
    extern __shared__ __align__(1024) char smem[];
    uint32_t sb = smem_to_u32(smem);
    int t = threadIdx.x, wid = t >> 5, lane = t & 31;

    int blk   = blockIdx.x;
    int b     = blk >> 8;
    int nbase = (blk & 255) * NPB;
    const float* Fb = features + (size_t)b * N_ * F_;

    int*   nbS  = (int*)(smem + SM_NBS);
    float* cenS = (float*)(smem + SM_CENS);
    float* b1s  = (float*)(smem + SM_B1S);
    float* b2s  = (float*)(smem + SM_B2S);

    for (int i = t; i < NPB * F_; i += THR)
        cenS[i] = Fb[(size_t)(nbase + (i >> 6)) * F_ + (i & 63)];
    if (t < M_) nbS[t] = g_idx[((size_t)b * N_ + nbase + (t >> 4)) * K_ + (t & 15)];
    b1s[t] = b1[t];
    if (t < P_) b2s[t] = b2[t];
    __syncthreads();

    // ---- build A image (hi/lo bf16, swizzled): 64 rows x 128 cols ----
    for (int i = t; i < 2048; i += THR) {
        int m  = i >> 5;
        int fg = (i & 31) << 2;
        float v0, v1, v2, v3;
        if (fg < 64) {
            float4 nv = *(const float4*)(Fb + (size_t)nbS[m] * F_ + fg);
            float4 cv = *(const float4*)(cenS + (m >> 4) * F_ + fg);
            v0 = nv.x - cv.x; v1 = nv.y - cv.y; v2 = nv.z - cv.z; v3 = nv.w - cv.w;
        } else {
            float4 cv = *(const float4*)(cenS + (m >> 4) * F_ + (fg - 64));
            v0 = cv.x; v1 = cv.y; v2 = cv.z; v3 = cv.w;
        }
        ull hi, lo; split4(v0, v1, v2, v3, hi, lo);
        uint32_t off = img_off(m, fg);
        *(ull*)(smem + SM_AHI + off) = hi;
        *(ull*)(smem + SM_ALO + off) = lo;
    }
    __syncthreads();

    int wm = wid & 1, wg = wid >> 1;      // 2 M-groups x 4 N-groups
    int m0 = wm * 32;
    int n0 = wg * 32;

    // ================= phase 1: both halves -> full H image =================
#pragma unroll 1
    for (int h = 0; h < 2; h++) {
        float d[2][4][4];
#pragma unroll
        for (int mt = 0; mt < 2; mt++)
#pragma unroll
            for (int nt = 0; nt < 4; nt++)
#pragma unroll
                for (int r = 0; r < 4; r++) d[mt][nt][r] = 0.0f;

#pragma unroll 1
        for (int ks = 0; ks < 8; ks++) {
            uint32_t ahi[2][4], alo[2][4];
#pragma unroll
            for (int mt = 0; mt < 2; mt++) {
                int row = m0 + mt * 16 + (lane & 15);
                int ch  = ks * 2 + (lane >> 4);
                ldm_x4(ahi[mt], img_addr(sb + SM_AHI, row, ch));
                ldm_x4(alo[mt], img_addr(sb + SM_ALO, row, ch));
            }
            const uint4* wf = g_w1f + (((h * 8 + ks) * 16) + wg * 4) * 32 + lane;
#pragma unroll
            for (int nt = 0; nt < 4; nt++) {
                uint4 frag = wf[nt * 32];
#pragma unroll
                for (int mt = 0; mt < 2; mt++) {
                    mma_bf16(d[mt][nt], ahi[mt], frag.x, frag.y);
                    mma_bf16(d[mt][nt], ahi[mt], frag.z, frag.w);
                    mma_bf16(d[mt][nt], alo[mt], frag.x, frag.y);
                }
            }
        }

        // epilogue: bias + gelu -> H image (full 256-col layout), no barrier
#pragma unroll
        for (int mt = 0; mt < 2; mt++) {
            int row0 = m0 + mt * 16 + (lane >> 2);
#pragma unroll
            for (int nt = 0; nt < 4; nt++) {
                int colb = n0 + nt * 8 + (lane & 3) * 2;
                float bv0 = b1s[h * 128 + colb], bv1 = b1s[h * 128 + colb + 1];
                float v0 = gelu_exact(d[mt][nt][0] + bv0);
                float v1 = gelu_exact(d[mt][nt][1] + bv1);
                float v2 = gelu_exact(d[mt][nt][2] + bv0);
                float v3 = gelu_exact(d[mt][nt][3] + bv1);
                int colg = h * 128 + colb;
                uint32_t hi, lo;
                split2(v0, v1, hi, lo);
                uint32_t off = img_off256(row0, colg);
                *(uint32_t*)(smem + SM_HHI + off) = hi;
                *(uint32_t*)(smem + SM_HLO + off) = lo;
                split2(v2, v3, hi, lo);
                off = img_off256(row0 + 8, colg);
                *(uint32_t*)(smem + SM_HHI + off) = hi;
                *(uint32_t*)(smem + SM_HLO + off) = lo;
            }
        }
    }
    __syncthreads();

    // ================= phase 2: H[64x256] @ W2 -> e (16 ks) =================
    float e[2][4][4];
#pragma unroll
    for (int mt = 0; mt < 2; mt++)
#pragma unroll
        for (int nt = 0; nt < 4; nt++)
#pragma unroll
            for (int r = 0; r < 4; r++) e[mt][nt][r] = 0.0f;

#pragma unroll 1
    for (int ks = 0; ks < 16; ks++) {
        uint32_t ahi[2][4], alo[2][4];
#pragma unroll
        for (int mt = 0; mt < 2; mt++) {
            int row = m0 + mt * 16 + (lane & 15);
            int ch  = ks * 2 + (lane >> 4);
            ldm_x4(ahi[mt], img_addr256(sb + SM_HHI, row, ch));
            ldm_x4(alo[mt], img_addr256(sb + SM_HLO, row, ch));
        }
        const uint4* wf = g_w2f + ((ks * 16) + wg * 4) * 32 + lane;
#pragma unroll
        for (int nt = 0; nt < 4; nt++) {
            uint4 frag = wf[nt * 32];
#pragma unroll
            for (int mt = 0; mt < 2; mt++) {
                mma_bf16(e[mt][nt], ahi[mt], frag.x, frag.y);
                mma_bf16(e[mt][nt], ahi[mt], frag.z, frag.w);
                mma_bf16(e[mt][nt], alo[mt], frag.x, frag.y);
            }
        }
    }

    // ---- final epilogue: bias + gelu + mean over 16 edges ----
#pragma unroll
    for (int mt = 0; mt < 2; mt++) {
        int pl = wm * 2 + mt;                  // local point 0..3
#pragma unroll
        for (int nt = 0; nt < 4; nt++) {
            int colb = n0 + nt * 8 + (lane & 3) * 2;
            float bv0 = b2s[colb], bv1 = b2s[colb + 1];
            float s0 = gelu_exact(e[mt][nt][0] + bv0) + gelu_exact(e[mt][nt][2] + bv0);
            float s1 = gelu_exact(e[mt][nt][1] + bv1) + gelu_exact(e[mt][nt][3] + bv1);
            s0 += __shfl_down_sync(0xffffffffu, s0, 16);
            s0 += __shfl_down_sync(0xffffffffu, s0, 8);
            s0 += __shfl_down_sync(0xffffffffu, s0, 4);
            s1 += __shfl_down_sync(0xffffffffu, s1, 16);
            s1 += __shfl_down_sync(0xffffffffu, s1, 8);
            s1 += __shfl_down_sync(0xffffffffu, s1, 4);
            if (lane < 4) {
                float* op = out + ((size_t)b * N_ + nbase + pl) * P_ + colb;
                op[0] = s0 * (1.0f / 16.0f);
                op[1] = s1 * (1.0f / 16.0f);
            }
        }
    }
}

// ---------------------------------------------------------------------------
extern "C" void kernel_launch(void* const* d_in, const int* in_sizes, int n_in,
                              void* d_out, int out_size)
{
    const float* points   = (const float*)d_in[0];
    const float* features = (const float*)d_in[1];
    const float* W1       = (const float*)d_in[2];
    const float* b1       = (const float*)d_in[3];
    const float* W2       = (const float*)d_in[4];
    const float* b2       = (const float*)d_in[5];
    float* out = (float*)d_out;

    cudaFuncSetAttribute(mlp_kernel, cudaFuncAttributeMaxDynamicSharedMemorySize,
                         SMEM_TOTAL);

    prep_kernel<<<64, 256>>>(W1, W2);
    knn_kernel<<<B_ * 4, 256>>>(points);
    mlp_kernel<<<(B_ * N_) / NPB, THR, SMEM_TOTAL>>>(features, b1, b2, out);
}

// round 17
// speedup vs baseline: 1.3188x; 1.3188x over previous
#include <cuda_runtime.h>
#include <cuda_fp16.h>
#include <math_constants.h>
#include <cstdint>

#define B_   32
#define N_   1024
#define F_   64
#define K_   16
#define P_   128
#define H_   256
#define NPB  4              // points per block
#define M_   64             // GEMM rows per block
#define THR  256            // 8 warps

typedef unsigned long long ull;

// ---------------------------------------------------------------------------
// device scratch (static — no allocation)
// Fragment tables: 8B per (ks, ntile, lane) = {b0, b1} fp16x2
// ---------------------------------------------------------------------------
__device__ int g_idx[B_ * N_ * K_];
__device__ __align__(16) uint2 g_w1f[2 * 8 * 16 * 32];   // 32 KB
__device__ __align__(16) uint2 g_w2f[2 * 8 * 16 * 32];   // 32 KB (ks_glob = h*8+ks)

// ---------------------------------------------------------------------------
// SMEM layout (dynamic, bytes)
// A image: 64 rows x 128 cols fp16 (256B/row)
// H image: 64 rows x 128 cols fp16 (current half)
// ---------------------------------------------------------------------------
#define SM_A    0            // 16384
#define SM_H    16384        // 16384
#define SM_MISC 32768
#define SM_NBS  (SM_MISC + 0)        // 64 ints
#define SM_CENS (SM_MISC + 256)      // 256 floats
#define SM_B1S  (SM_MISC + 1280)     // 256 floats
#define SM_B2S  (SM_MISC + 2304)     // 128 floats
#define SMEM_TOTAL (SM_MISC + 2816)

// ---------------------------------------------------------------------------
// image addressing: row-major [rows][128 fp16], 256B/row,
// 16B chunks XOR-swizzled by row&7 -> conflict-free ldmatrix
// ---------------------------------------------------------------------------
__device__ __forceinline__ uint32_t img_off(int r, int c)
{
    return (uint32_t)(r * 256) + (uint32_t)((((c >> 3) ^ (r & 7)) << 4) + (c & 7) * 2);
}
__device__ __forceinline__ uint32_t img_addr(uint32_t base, int row, int chunk)
{
    return base + (uint32_t)(row * 256) + (uint32_t)(((chunk ^ (row & 7)) << 4));
}

__device__ __forceinline__ uint32_t smem_to_u32(const void* p)
{
    uint32_t a;
    asm("{ .reg .u64 t; cvta.to.shared.u64 t, %1; cvt.u32.u64 %0, t; }"
        : "=r"(a) : "l"(p));
    return a;
}

// ---------------------------------------------------------------------------
// ldmatrix / mma wrappers (baseline PTX, no sm_103a-gated features)
// ---------------------------------------------------------------------------
__device__ __forceinline__ void ldm_x4(uint32_t* r, uint32_t addr)
{
    asm volatile("ldmatrix.sync.aligned.m8n8.x4.shared.b16 {%0,%1,%2,%3}, [%4];"
                 : "=r"(r[0]), "=r"(r[1]), "=r"(r[2]), "=r"(r[3]) : "r"(addr));
}
__device__ __forceinline__ void mma_f16(float* d, const uint32_t* a,
                                        uint32_t b0, uint32_t b1)
{
    asm volatile(
        "mma.sync.aligned.m16n8k16.row.col.f32.f16.f16.f32 "
        "{%0,%1,%2,%3}, {%4,%5,%6,%7}, {%8,%9}, {%0,%1,%2,%3};"
        : "+f"(d[0]), "+f"(d[1]), "+f"(d[2]), "+f"(d[3])
        : "r"(a[0]), "r"(a[1]), "r"(a[2]), "r"(a[3]), "r"(b0), "r"(b1));
}

// pack two fp32 -> fp16x2 (lo in lower 16 bits). First PTX source = upper half.
__device__ __forceinline__ uint32_t pkh2(float lo, float hi)
{
    uint32_t r;
    asm("cvt.rn.f16x2.f32 %0, %2, %1;" : "=r"(r) : "f"(lo), "f"(hi));
    return r;
}
__device__ __forceinline__ float gelu_exact(float x)
{
    return 0.5f * x * (1.0f + erff(x * 0.70710678118654752440f));
}

// ---------------------------------------------------------------------------
// Kernel 0: weight prep — build fp16 B-fragment tables.
// Fragment spec m16n8k16 'col' B: n' = lane>>2, k0 = 2*(lane&3); b1: k0+8.
// ---------------------------------------------------------------------------
__global__ __launch_bounds__(256) void prep_kernel(const float* __restrict__ W1,
                                                   const float* __restrict__ W2)
{
    int i = blockIdx.x * 256 + threadIdx.x;      // 0 .. 16383
    int mat  = i >> 13;
    int rem  = i & 8191;
    int h    = rem >> 12;
    int ks   = (rem >> 9) & 7;
    int nt   = (rem >> 5) & 15;
    int lane = rem & 31;

    int np = nt * 8 + (lane >> 2);
    int k0 = ks * 16 + (lane & 3) * 2;

    float v[4];
    if (mat == 0) {
        int n = h * 128 + np;
        v[0] = W1[(k0 + 0) * H_ + n];
        v[1] = W1[(k0 + 1) * H_ + n];
        v[2] = W1[(k0 + 8) * H_ + n];
        v[3] = W1[(k0 + 9) * H_ + n];
    } else {
        int j = h * 128 + k0;
        v[0] = W2[(j + 0) * P_ + np];
        v[1] = W2[(j + 1) * P_ + np];
        v[2] = W2[(j + 8) * P_ + np];
        v[3] = W2[(j + 9) * P_ + np];
    }
    uint2 frag;
    frag.x = pkh2(v[0], v[1]);
    frag.y = pkh2(v[2], v[3]);

    int idx = (((h * 8 + ks) * 16) + nt) * 32 + lane;
    if (mat == 0) g_w1f[idx] = frag;
    else          g_w2f[idx] = frag;
}

// ---------------------------------------------------------------------------
// Kernel 1: KNN (proven correct, unchanged)
// ---------------------------------------------------------------------------
__global__ __launch_bounds__(256) void knn_kernel(const float* __restrict__ points)
{
    __shared__ float4 pts[N_];
    int b = blockIdx.x >> 2;
    int rowbase = (blockIdx.x & 3) << 8;
    const float* P = points + (size_t)b * N_ * 3;
    for (int i = threadIdx.x; i < N_; i += 256) {
        float x = P[i * 3 + 0], y = P[i * 3 + 1], z = P[i * 3 + 2];
        pts[i] = make_float4(x, y, z, x * x + y * y + z * z);
    }
    __syncthreads();

    int n = rowbase + threadIdx.x;
    float4 pn = pts[n];

    float dist[K_ + 1];
    int   nbr[K_ + 1];
#pragma unroll
    for (int j = 0; j <= K_; j++) { dist[j] = CUDART_INF_F; nbr[j] = 0; }
    float worst = CUDART_INF_F;

    for (int m = 0; m < N_; m++) {
        float4 pm = pts[m];
        float dot = pn.x * pm.x + pn.y * pm.y + pn.z * pm.z;
        float d = pn.w - 2.0f * dot + pm.w + 1e-5f;
        if (d < worst) {
            int j = K_;
            for (; j > 0; j--) {
                if (dist[j - 1] > d) { dist[j] = dist[j - 1]; nbr[j] = nbr[j - 1]; }
                else break;
            }
            dist[j] = d; nbr[j] = m;
            worst = dist[K_];
        }
    }

    int* o = g_idx + ((size_t)b * N_ + n) * K_;
#pragma unroll
    for (int k = 0; k < K_; k++) o[k] = nbr[k + 1];
}

// ---------------------------------------------------------------------------
// Kernel 2: fused edge-MLP via fp16 mma.sync (single product, fp32 acc).
// Structure and ordering identical to R14 (proven fastest); only the
// precision scheme changed: bf16 3-product split -> fp16 single product.
// ---------------------------------------------------------------------------
__global__ __launch_bounds__(THR, 2) void mlp_kernel(
    const float* __restrict__ features,
    const float* __restrict__ b1, const float* __restrict__ b2,
    float* __restrict__ out)
{
    extern __shared__ __align__(1024) char smem[];
    uint32_t sb = smem_to_u32(smem);
    int t = threadIdx.x, wid = t >> 5, lane = t & 31;

    int blk   = blockIdx.x;
    int b     = blk >> 8;
    int nbase = (blk & 255) * NPB;
    const float* Fb = features + (size_t)b * N_ * F_;

    int*   nbS  = (int*)(smem + SM_NBS);
    float* cenS = (float*)(smem + SM_CENS);
    float* b1s  = (float*)(smem + SM_B1S);
    float* b2s  = (float*)(smem + SM_B2S);

    for (int i = t; i < NPB * F_; i += THR)
        cenS[i] = Fb[(size_t)(nbase + (i >> 6)) * F_ + (i & 63)];
    if (t < M_) nbS[t] = g_idx[((size_t)b * N_ + nbase + (t >> 4)) * K_ + (t & 15)];
    b1s[t] = b1[t];
    if (t < P_) b2s[t] = b2[t];
    __syncthreads();

    // ---- build A image (fp16, swizzled): 64 rows x 128 cols ----
    for (int i = t; i < 2048; i += THR) {
        int m  = i >> 5;
        int fg = (i & 31) << 2;
        float v0, v1, v2, v3;
        if (fg < 64) {
            float4 nv = *(const float4*)(Fb + (size_t)nbS[m] * F_ + fg);
            float4 cv = *(const float4*)(cenS + (m >> 4) * F_ + fg);
            v0 = nv.x - cv.x; v1 = nv.y - cv.y; v2 = nv.z - cv.z; v3 = nv.w - cv.w;
        } else {
            float4 cv = *(const float4*)(cenS + (m >> 4) * F_ + (fg - 64));
            v0 = cv.x; v1 = cv.y; v2 = cv.z; v3 = cv.w;
        }
        ull p = (ull)pkh2(v0, v1) | ((ull)pkh2(v2, v3) << 32);
        *(ull*)(smem + SM_A + img_off(m, fg)) = p;
    }

    int wm = wid & 1, wg = wid >> 1;      // 2 M-groups x 4 N-groups
    int m0 = wm * 32;
    int n0 = wg * 32;

    float e[2][4][4];
#pragma unroll
    for (int mt = 0; mt < 2; mt++)
#pragma unroll
        for (int nt = 0; nt < 4; nt++)
#pragma unroll
            for (int r = 0; r < 4; r++) e[mt][nt][r] = 0.0f;

#pragma unroll 1
    for (int h = 0; h < 2; h++) {
        __syncthreads();

        // ---- phase 1: A[64x128] @ W1half -> d ----
        float d[2][4][4];
#pragma unroll
        for (int mt = 0; mt < 2; mt++)
#pragma unroll
            for (int nt = 0; nt < 4; nt++)
#pragma unroll
                for (int r = 0; r < 4; r++) d[mt][nt][r] = 0.0f;

#pragma unroll 1
        for (int ks = 0; ks < 8; ks++) {
            uint32_t af[2][4];
#pragma unroll
            for (int mt = 0; mt < 2; mt++) {
                int row = m0 + mt * 16 + (lane & 15);
                int ch  = ks * 2 + (lane >> 4);
                ldm_x4(af[mt], img_addr(sb + SM_A, row, ch));
            }
            const uint2* wf = g_w1f + (((h * 8 + ks) * 16) + wg * 4) * 32 + lane;
#pragma unroll
            for (int nt = 0; nt < 4; nt++) {
                uint2 frag = wf[nt * 32];
#pragma unroll
                for (int mt = 0; mt < 2; mt++)
                    mma_f16(d[mt][nt], af[mt], frag.x, frag.y);
            }
        }

        // ---- epilogue: bias + gelu -> H image (fp16) ----
#pragma unroll
        for (int mt = 0; mt < 2; mt++) {
            int row0 = m0 + mt * 16 + (lane >> 2);
#pragma unroll
            for (int nt = 0; nt < 4; nt++) {
                int colb = n0 + nt * 8 + (lane & 3) * 2;
                float bv0 = b1s[h * 128 + colb], bv1 = b1s[h * 128 + colb + 1];
                float v0 = gelu_exact(d[mt][nt][0] + bv0);
                float v1 = gelu_exact(d[mt][nt][1] + bv1);
                float v2 = gelu_exact(d[mt][nt][2] + bv0);
                float v3 = gelu_exact(d[mt][nt][3] + bv1);
                *(uint32_t*)(smem + SM_H + img_off(row0,     colb)) = pkh2(v0, v1);
                *(uint32_t*)(smem + SM_H + img_off(row0 + 8, colb)) = pkh2(v2, v3);
            }
        }
        __syncthreads();

        // ---- phase 2 partial: H[64x128] @ W2chunk(h) -> e ----
#pragma unroll 1
        for (int ks = 0; ks < 8; ks++) {
            uint32_t af[2][4];
#pragma unroll
            for (int mt = 0; mt < 2; mt++) {
                int row = m0 + mt * 16 + (lane & 15);
                int ch  = ks * 2 + (lane >> 4);
                ldm_x4(af[mt], img_addr(sb + SM_H, row, ch));
            }
            const uint2* wf = g_w2f + (((h * 8 + ks) * 16) + wg * 4) * 32 + lane;
#pragma unroll
            for (int nt = 0; nt < 4; nt++) {
                uint2 frag = wf[nt * 32];
#pragma unroll
                for (int mt = 0; mt < 2; mt++)
                    mma_f16(e[mt][nt], af[mt], frag.x, frag.y);
            }
        }
    }

    // ---- final epilogue: bias + gelu + mean over 16 edges ----
#pragma unroll
    for (int mt = 0; mt < 2; mt++) {
        int pl = wm * 2 + mt;                  // local point 0..3
#pragma unroll
        for (int nt = 0; nt < 4; nt++) {
            int colb = n0 + nt * 8 + (lane & 3) * 2;
            float bv0 = b2s[colb], bv1 = b2s[colb + 1];
            float s0 = gelu_exact(e[mt][nt][0] + bv0) + gelu_exact(e[mt][nt][2] + bv0);
            float s1 = gelu_exact(e[mt][nt][1] + bv1) + gelu_exact(e[mt][nt][3] + bv1);
            s0 += __shfl_down_sync(0xffffffffu, s0, 16);
            s0 += __shfl_down_sync(0xffffffffu, s0, 8);
            s0 += __shfl_down_sync(0xffffffffu, s0, 4);
            s1 += __shfl_down_sync(0xffffffffu, s1, 16);
            s1 += __shfl_down_sync(0xffffffffu, s1, 8);
            s1 += __shfl_down_sync(0xffffffffu, s1, 4);
            if (lane < 4) {
                float* op = out + ((size_t)b * N_ + nbase + pl) * P_ + colb;
                op[0] = s0 * (1.0f / 16.0f);
                op[1] = s1 * (1.0f / 16.0f);
            }
        }
    }
}

// ---------------------------------------------------------------------------
extern "C" void kernel_launch(void* const* d_in, const int* in_sizes, int n_in,
                              void* d_out, int out_size)
{
    const float* points   = (const float*)d_in[0];
    const float* features = (const float*)d_in[1];
    const float* W1       = (const float*)d_in[2];
    const float* b1       = (const float*)d_in[3];
    const float* W2       = (const float*)d_in[4];
    const float* b2       = (const float*)d_in[5];
    float* out = (float*)d_out;

    cudaFuncSetAttribute(mlp_kernel, cudaFuncAttributeMaxDynamicSharedMemorySize,
                         SMEM_TOTAL);

    prep_kernel<<<64, 256>>>(W1, W2);
    knn_kernel<<<B_ * 4, 256>>>(points);
    mlp_kernel<<<(B_ * N_) / NPB, THR, SMEM_TOTAL>>>(features, b1, b2, out);
}